// round 10
// baseline (speedup 1.0000x reference)
#include <cuda_runtime.h>
#include <math_constants.h>

#define NFEAT 65536
#define FD    512
#define NC    256
#define RPC   (NFEAT / NC)      // 256 rows per class
#define F4D   (FD / 4)          // 128 float4 per row
#define RSPLIT 8                // row-chunks per class
#define RCHUNK (RPC / RSPLIT)   // 32 rows per chunk
#define NIT    32               // i-tiles (8 rows each)
#define NJT    4                // j-tiles (64 cols each)
#define NBLK2  (NIT * NJT)      // 128 sim blocks

// Scratch (no cudaMalloc allowed)
__device__ float g_partial[RSPLIT * NC * FD];  // 4 MB partial sums
__device__ float g_centers[NC * FD];           // normalized centers [j][k]
__device__ float g_centersT[FD * NC];          // normalized centers [k][j]
__device__ float g_partmin[NJT * NC];          // per-(jtile,row) partial min
__device__ unsigned int g_cnt2;                // sim fan-in counter

// ---------------------------------------------------------------------------
// Kernel 1: partial row-sums. grid = 2048, block = 128. At the measured
// LTS/HBM ceiling (~5.75 TB/s) -- leave alone.
// ---------------------------------------------------------------------------
__global__ void __launch_bounds__(128) centers_partial_kernel(const float* __restrict__ feat) {
    const int b = blockIdx.x;
    const int c = b >> 3;
    const int s = b & 7;
    const int t = threadIdx.x;

    const float4* __restrict__ p =
        reinterpret_cast<const float4*>(feat)
        + ((size_t)c * RPC + (size_t)s * RCHUNK) * F4D + t;

    float4 acc = make_float4(0.f, 0.f, 0.f, 0.f);
    #pragma unroll
    for (int r0 = 0; r0 < RCHUNK; r0 += 8) {
        float4 b0 = __ldcs(p + (size_t)(r0 + 0) * F4D);
        float4 b1 = __ldcs(p + (size_t)(r0 + 1) * F4D);
        float4 b2 = __ldcs(p + (size_t)(r0 + 2) * F4D);
        float4 b3 = __ldcs(p + (size_t)(r0 + 3) * F4D);
        float4 b4 = __ldcs(p + (size_t)(r0 + 4) * F4D);
        float4 b5 = __ldcs(p + (size_t)(r0 + 5) * F4D);
        float4 b6 = __ldcs(p + (size_t)(r0 + 6) * F4D);
        float4 b7 = __ldcs(p + (size_t)(r0 + 7) * F4D);
        acc.x += b0.x; acc.y += b0.y; acc.z += b0.z; acc.w += b0.w;
        acc.x += b1.x; acc.y += b1.y; acc.z += b1.z; acc.w += b1.w;
        acc.x += b2.x; acc.y += b2.y; acc.z += b2.z; acc.w += b2.w;
        acc.x += b3.x; acc.y += b3.y; acc.z += b3.z; acc.w += b3.w;
        acc.x += b4.x; acc.y += b4.y; acc.z += b4.z; acc.w += b4.w;
        acc.x += b5.x; acc.y += b5.y; acc.z += b5.z; acc.w += b5.w;
        acc.x += b6.x; acc.y += b6.y; acc.z += b6.z; acc.w += b6.w;
        acc.x += b7.x; acc.y += b7.y; acc.z += b7.z; acc.w += b7.w;
    }
    reinterpret_cast<float4*>(g_partial)[((size_t)s * NC + c) * F4D + t] = acc;
}

// ---------------------------------------------------------------------------
// Kernel 2: fold partials, mean, L2-norm; write row-major + transposed.
// grid = 256, block = 128.
// ---------------------------------------------------------------------------
__global__ void __launch_bounds__(128) centers_finalize_kernel() {
    const int c = blockIdx.x;
    const int t = threadIdx.x;

    float4 sum = make_float4(0.f, 0.f, 0.f, 0.f);
    #pragma unroll
    for (int k = 0; k < RSPLIT; ++k) {
        float4 v = reinterpret_cast<const float4*>(g_partial)[((size_t)k * NC + c) * F4D + t];
        sum.x += v.x; sum.y += v.y; sum.z += v.z; sum.w += v.w;
    }
    const float inv = 1.0f / (float)RPC;
    sum.x *= inv; sum.y *= inv; sum.z *= inv; sum.w *= inv;

    float ss = sum.x*sum.x + sum.y*sum.y + sum.z*sum.z + sum.w*sum.w;
    #pragma unroll
    for (int o = 16; o > 0; o >>= 1)
        ss += __shfl_xor_sync(0xffffffffu, ss, o);

    __shared__ float sred[4];
    if ((t & 31) == 0) sred[t >> 5] = ss;
    __syncthreads();
    float total = sred[0] + sred[1] + sred[2] + sred[3];
    float invn = 1.0f / fmaxf(sqrtf(total), 1e-8f);

    float4 o4 = make_float4(sum.x * invn, sum.y * invn, sum.z * invn, sum.w * invn);
    reinterpret_cast<float4*>(g_centers)[(size_t)c * F4D + t] = o4;

    g_centersT[(size_t)(4 * t + 0) * NC + c] = o4.x;
    g_centersT[(size_t)(4 * t + 1) * NC + c] = o4.y;
    g_centersT[(size_t)(4 * t + 2) * NC + c] = o4.z;
    g_centersT[(size_t)(4 * t + 3) * NC + c] = o4.w;
}

// ---------------------------------------------------------------------------
// Kernel 3: sim partial row mins. 8 i-rows x 64 j per block -> 128 blocks;
// halves CT L2 traffic vs 4-i-row tiling (32MB -> 16MB) and doubles FMA
// density per loaded byte (32 accumulators/thread).
// Thread: jq = t&15 owns float4 j-group, ks = t>>4 owns k in [32ks,32ks+32).
// Last block: min over j-tiles per row, sum(1 - min) -> out[0].
// ---------------------------------------------------------------------------
#define SIM_STEP8(A0, A1, A2, A3, A4, A5, A6, A7, V)                         \
    acc[0][0] += (A0)*(V).x; acc[0][1] += (A0)*(V).y;                        \
    acc[0][2] += (A0)*(V).z; acc[0][3] += (A0)*(V).w;                        \
    acc[1][0] += (A1)*(V).x; acc[1][1] += (A1)*(V).y;                        \
    acc[1][2] += (A1)*(V).z; acc[1][3] += (A1)*(V).w;                        \
    acc[2][0] += (A2)*(V).x; acc[2][1] += (A2)*(V).y;                        \
    acc[2][2] += (A2)*(V).z; acc[2][3] += (A2)*(V).w;                        \
    acc[3][0] += (A3)*(V).x; acc[3][1] += (A3)*(V).y;                        \
    acc[3][2] += (A3)*(V).z; acc[3][3] += (A3)*(V).w;                        \
    acc[4][0] += (A4)*(V).x; acc[4][1] += (A4)*(V).y;                        \
    acc[4][2] += (A4)*(V).z; acc[4][3] += (A4)*(V).w;                        \
    acc[5][0] += (A5)*(V).x; acc[5][1] += (A5)*(V).y;                        \
    acc[5][2] += (A5)*(V).z; acc[5][3] += (A5)*(V).w;                        \
    acc[6][0] += (A6)*(V).x; acc[6][1] += (A6)*(V).y;                        \
    acc[6][2] += (A6)*(V).z; acc[6][3] += (A6)*(V).w;                        \
    acc[7][0] += (A7)*(V).x; acc[7][1] += (A7)*(V).y;                        \
    acc[7][2] += (A7)*(V).z; acc[7][3] += (A7)*(V).w;

__global__ void __launch_bounds__(256) sim_kernel(float* __restrict__ out) {
    const int blk = blockIdx.x;
    const int bi  = blk & (NIT - 1);           // i-tile 0..31
    const int jt  = blk >> 5;                  // j-tile 0..3
    const int ib  = bi * 8;                    // i rows [ib, ib+8)
    const int t   = threadIdx.x;
    const int jq  = t & 15;                    // j float4-group within tile
    const int ks  = t >> 4;                    // k-slice 0..15

    __shared__ float4 sc4[8][F4D];             // 16 KB: i-rows
    __shared__ float4 red4[256 * 8];           // 32 KB: per-thread partials
    {
        const float4* src = reinterpret_cast<const float4*>(g_centers + (size_t)ib * FD);
        for (int k = t; k < 8 * F4D; k += 256)
            sc4[k >> 7][k & 127] = src[k];
    }
    __syncthreads();

    const float4* __restrict__ ct = reinterpret_cast<const float4*>(g_centersT);
    const int col = jt * 16 + jq;              // float4 column in CT row

    float acc[8][4];
    #pragma unroll
    for (int i = 0; i < 8; ++i)
        #pragma unroll
        for (int j = 0; j < 4; ++j) acc[i][j] = 0.f;

    const int kb = ks * 32;
    float4 buf[2][4];
    #pragma unroll
    for (int u = 0; u < 4; ++u)
        buf[0][u] = __ldcg(&ct[(size_t)(kb + u) * (NC / 4) + col]);

    #pragma unroll
    for (int ch = 0; ch < 8; ++ch) {
        const int pb = ch & 1;
        if (ch < 7) {
            const int k2 = kb + (ch + 1) * 4;
            #pragma unroll
            for (int u = 0; u < 4; ++u)
                buf[pb ^ 1][u] = __ldcg(&ct[(size_t)(k2 + u) * (NC / 4) + col]);
        }
        const int kf = (kb + ch * 4) >> 2;     // one float4-k per chunk
        float4 a0 = sc4[0][kf];
        float4 a1 = sc4[1][kf];
        float4 a2 = sc4[2][kf];
        float4 a3 = sc4[3][kf];
        float4 a4 = sc4[4][kf];
        float4 a5 = sc4[5][kf];
        float4 a6 = sc4[6][kf];
        float4 a7 = sc4[7][kf];
        SIM_STEP8(a0.x, a1.x, a2.x, a3.x, a4.x, a5.x, a6.x, a7.x, buf[pb][0]);
        SIM_STEP8(a0.y, a1.y, a2.y, a3.y, a4.y, a5.y, a6.y, a7.y, buf[pb][1]);
        SIM_STEP8(a0.z, a1.z, a2.z, a3.z, a4.z, a5.z, a6.z, a7.z, buf[pb][2]);
        SIM_STEP8(a0.w, a1.w, a2.w, a3.w, a4.w, a5.w, a6.w, a7.w, buf[pb][3]);
    }

    #pragma unroll
    for (int i = 0; i < 8; ++i)
        red4[(size_t)t * 8 + i] = make_float4(acc[i][0], acc[i][1], acc[i][2], acc[i][3]);
    __syncthreads();

    __shared__ float s_min[8][16];
    if (t < 128) {                             // thread = (i = t>>4, jq2 = t&15)
        const int i   = t >> 4;
        const int jq2 = t & 15;
        float4 s = make_float4(0.f, 0.f, 0.f, 0.f);
        #pragma unroll
        for (int k2 = 0; k2 < 16; ++k2) {
            float4 v = red4[(size_t)(k2 * 16 + jq2) * 8 + i];
            s.x += v.x; s.y += v.y; s.z += v.z; s.w += v.w;
        }
        const int ig = ib + i;
        const int jb = jt * 64 + 4 * jq2;
        float m = CUDART_INF_F;
        if (jb + 0 != ig) m = fminf(m, s.x);
        if (jb + 1 != ig) m = fminf(m, s.y);
        if (jb + 2 != ig) m = fminf(m, s.z);
        if (jb + 3 != ig) m = fminf(m, s.w);
        s_min[i][jq2] = m;
    }
    __syncthreads();
    if (t < 8) {
        float m = CUDART_INF_F;
        #pragma unroll
        for (int q = 0; q < 16; ++q) m = fminf(m, s_min[t][q]);
        g_partmin[(size_t)jt * NC + ib + t] = m;
    }

    // fan-in: last block computes sum(1 - min over jt) into out[0]
    __threadfence();
    __shared__ unsigned int s_prev;
    if (t == 0) s_prev = atomicAdd(&g_cnt2, 1u);
    __syncthreads();
    if (s_prev != NBLK2 - 1) return;
    __threadfence();

    float m = __ldcg(&g_partmin[t]);
    #pragma unroll
    for (int jt2 = 1; jt2 < NJT; ++jt2)
        m = fminf(m, __ldcg(&g_partmin[(size_t)jt2 * NC + t]));
    float v = 1.0f - m;

    #pragma unroll
    for (int o = 16; o > 0; o >>= 1)
        v += __shfl_xor_sync(0xffffffffu, v, o);

    __shared__ float sfin[8];
    if ((t & 31) == 0) sfin[t >> 5] = v;
    __syncthreads();
    if (t == 0) {
        float total = 0.f;
        #pragma unroll
        for (int i = 0; i < 8; ++i) total += sfin[i];
        out[0] = total;
        g_cnt2 = 0u;   // reset for next graph replay
    }
}

extern "C" void kernel_launch(void* const* d_in, const int* in_sizes, int n_in,
                              void* d_out, int out_size) {
    const float* feat = (const float*)d_in[0];
    float* out = (float*)d_out;

    centers_partial_kernel<<<NC * RSPLIT, 128>>>(feat);
    centers_finalize_kernel<<<NC, 128>>>();
    sim_kernel<<<NBLK2, 256>>>(out);
}

// round 11
// speedup vs baseline: 1.1150x; 1.1150x over previous
#include <cuda_runtime.h>
#include <math_constants.h>

#define NFEAT 65536
#define FD    512
#define NC    256
#define RPC   (NFEAT / NC)      // 256 rows per class
#define F4D   (FD / 4)          // 128 float4 per row
#define RSPLIT 8                // row-chunks per class
#define RCHUNK (RPC / RSPLIT)   // 32 rows per chunk
#define NJT    4                // j-tiles in sim
#define NBLK2  (64 * NJT)       // 256 sim blocks

// Scratch (no cudaMalloc allowed)
__device__ float g_partial[RSPLIT * NC * FD];  // 4 MB partial sums
__device__ float g_centers[NC * FD];           // normalized centers [j][k]
__device__ float g_centersT[FD * NC];          // normalized centers [k][j]
__device__ float g_partmin[NJT * NC];          // per-(jtile,row) partial min
__device__ unsigned int g_cnt2;                // sim fan-in counter

// ---------------------------------------------------------------------------
// Kernel 1: partial row-sums. grid = 2048, block = 128.
// At the measured LTS/HBM ceiling (~5.8 TB/s). Triggers PDL completion early.
// ---------------------------------------------------------------------------
__global__ void __launch_bounds__(128) centers_partial_kernel(const float* __restrict__ feat) {
    const int b = blockIdx.x;
    const int c = b >> 3;
    const int s = b & 7;
    const int t = threadIdx.x;

    const float4* __restrict__ p =
        reinterpret_cast<const float4*>(feat)
        + ((size_t)c * RPC + (size_t)s * RCHUNK) * F4D + t;

    float4 acc = make_float4(0.f, 0.f, 0.f, 0.f);
    #pragma unroll
    for (int r0 = 0; r0 < RCHUNK; r0 += 8) {
        float4 b0 = __ldcs(p + (size_t)(r0 + 0) * F4D);
        float4 b1 = __ldcs(p + (size_t)(r0 + 1) * F4D);
        float4 b2 = __ldcs(p + (size_t)(r0 + 2) * F4D);
        float4 b3 = __ldcs(p + (size_t)(r0 + 3) * F4D);
        float4 b4 = __ldcs(p + (size_t)(r0 + 4) * F4D);
        float4 b5 = __ldcs(p + (size_t)(r0 + 5) * F4D);
        float4 b6 = __ldcs(p + (size_t)(r0 + 6) * F4D);
        float4 b7 = __ldcs(p + (size_t)(r0 + 7) * F4D);
        acc.x += b0.x; acc.y += b0.y; acc.z += b0.z; acc.w += b0.w;
        acc.x += b1.x; acc.y += b1.y; acc.z += b1.z; acc.w += b1.w;
        acc.x += b2.x; acc.y += b2.y; acc.z += b2.z; acc.w += b2.w;
        acc.x += b3.x; acc.y += b3.y; acc.z += b3.z; acc.w += b3.w;
        acc.x += b4.x; acc.y += b4.y; acc.z += b4.z; acc.w += b4.w;
        acc.x += b5.x; acc.y += b5.y; acc.z += b5.z; acc.w += b5.w;
        acc.x += b6.x; acc.y += b6.y; acc.z += b6.z; acc.w += b6.w;
        acc.x += b7.x; acc.y += b7.y; acc.z += b7.z; acc.w += b7.w;
    }
    reinterpret_cast<float4*>(g_partial)[((size_t)s * NC + c) * F4D + t] = acc;

#if __CUDA_ARCH__ >= 900
    cudaTriggerProgrammaticLaunchCompletion();
#endif
}

// ---------------------------------------------------------------------------
// Kernel 2: fold partials, mean, L2-norm; write row-major + transposed.
// grid = 256, block = 128. PDL secondary: waits on K1 via grid-dependency.
// ---------------------------------------------------------------------------
__global__ void __launch_bounds__(128) centers_finalize_kernel() {
#if __CUDA_ARCH__ >= 900
    cudaGridDependencySynchronize();
#endif
    const int c = blockIdx.x;
    const int t = threadIdx.x;

    float4 sum = make_float4(0.f, 0.f, 0.f, 0.f);
    #pragma unroll
    for (int k = 0; k < RSPLIT; ++k) {
        float4 v = reinterpret_cast<const float4*>(g_partial)[((size_t)k * NC + c) * F4D + t];
        sum.x += v.x; sum.y += v.y; sum.z += v.z; sum.w += v.w;
    }
    const float inv = 1.0f / (float)RPC;
    sum.x *= inv; sum.y *= inv; sum.z *= inv; sum.w *= inv;

    float ss = sum.x*sum.x + sum.y*sum.y + sum.z*sum.z + sum.w*sum.w;
    #pragma unroll
    for (int o = 16; o > 0; o >>= 1)
        ss += __shfl_xor_sync(0xffffffffu, ss, o);

    __shared__ float sred[4];
    if ((t & 31) == 0) sred[t >> 5] = ss;
    __syncthreads();
    float total = sred[0] + sred[1] + sred[2] + sred[3];
    float invn = 1.0f / fmaxf(sqrtf(total), 1e-8f);

    float4 o4 = make_float4(sum.x * invn, sum.y * invn, sum.z * invn, sum.w * invn);
    reinterpret_cast<float4*>(g_centers)[(size_t)c * F4D + t] = o4;

    g_centersT[(size_t)(4 * t + 0) * NC + c] = o4.x;
    g_centersT[(size_t)(4 * t + 1) * NC + c] = o4.y;
    g_centersT[(size_t)(4 * t + 2) * NC + c] = o4.z;
    g_centersT[(size_t)(4 * t + 3) * NC + c] = o4.w;

#if __CUDA_ARCH__ >= 900
    cudaTriggerProgrammaticLaunchCompletion();
#endif
}

// ---------------------------------------------------------------------------
// Kernel 3: sim partial row mins, j-tiled across 256 blocks + fan-in sum.
// PDL secondary: waits on finalize via grid-dependency.
// Block blk: i-tile bi = blk & 63 (rows ib..ib+3), j-tile jt = blk >> 6.
// ---------------------------------------------------------------------------
#define SIM_STEP(AV0, AV1, AV2, AV3, V)                                      \
    acc[0][0] += (AV0)*(V).x; acc[0][1] += (AV0)*(V).y;                      \
    acc[0][2] += (AV0)*(V).z; acc[0][3] += (AV0)*(V).w;                      \
    acc[1][0] += (AV1)*(V).x; acc[1][1] += (AV1)*(V).y;                      \
    acc[1][2] += (AV1)*(V).z; acc[1][3] += (AV1)*(V).w;                      \
    acc[2][0] += (AV2)*(V).x; acc[2][1] += (AV2)*(V).y;                      \
    acc[2][2] += (AV2)*(V).z; acc[2][3] += (AV2)*(V).w;                      \
    acc[3][0] += (AV3)*(V).x; acc[3][1] += (AV3)*(V).y;                      \
    acc[3][2] += (AV3)*(V).z; acc[3][3] += (AV3)*(V).w;

__global__ void __launch_bounds__(256) sim_kernel(float* __restrict__ out) {
    const int blk = blockIdx.x;
    const int bi  = blk & 63;
    const int jt  = blk >> 6;
    const int ib  = bi * 4;                    // i rows [ib, ib+4)
    const int t   = threadIdx.x;
    const int jq  = t & 15;                    // j float4-group within tile
    const int ks  = t >> 4;                    // k-slice 0..15

#if __CUDA_ARCH__ >= 900
    cudaGridDependencySynchronize();
#endif

    __shared__ float4 sc4[4][F4D];             // 8 KB: i-rows
    __shared__ float4 red4[256 * 4];           // 16 KB: per-thread partials
    {
        const float4* src = reinterpret_cast<const float4*>(g_centers + (size_t)ib * FD);
        #pragma unroll
        for (int k = t; k < 4 * F4D; k += 256)
            sc4[k >> 7][k & 127] = src[k];
    }
    __syncthreads();

    const float4* __restrict__ ct = reinterpret_cast<const float4*>(g_centersT);
    const int col = jt * 16 + jq;              // float4 column in CT row

    float acc[4][4];
    #pragma unroll
    for (int i = 0; i < 4; ++i)
        #pragma unroll
        for (int j = 0; j < 4; ++j) acc[i][j] = 0.f;

    const int kb = ks * 32;
    float4 buf[2][8];
    #pragma unroll
    for (int u = 0; u < 8; ++u)
        buf[0][u] = __ldcg(&ct[(size_t)(kb + u) * (NC / 4) + col]);

    #pragma unroll
    for (int ch = 0; ch < 4; ++ch) {
        const int pb = ch & 1;
        if (ch < 3) {
            const int k2 = kb + (ch + 1) * 8;
            #pragma unroll
            for (int u = 0; u < 8; ++u)
                buf[pb ^ 1][u] = __ldcg(&ct[(size_t)(k2 + u) * (NC / 4) + col]);
        }
        const int kf0 = (kb + ch * 8) >> 2;
        #pragma unroll
        for (int g = 0; g < 2; ++g) {
            const int kf = kf0 + g;
            float4 a0 = sc4[0][kf];
            float4 a1 = sc4[1][kf];
            float4 a2 = sc4[2][kf];
            float4 a3 = sc4[3][kf];
            SIM_STEP(a0.x, a1.x, a2.x, a3.x, buf[pb][g * 4 + 0]);
            SIM_STEP(a0.y, a1.y, a2.y, a3.y, buf[pb][g * 4 + 1]);
            SIM_STEP(a0.z, a1.z, a2.z, a3.z, buf[pb][g * 4 + 2]);
            SIM_STEP(a0.w, a1.w, a2.w, a3.w, buf[pb][g * 4 + 3]);
        }
    }

    #pragma unroll
    for (int i = 0; i < 4; ++i)
        red4[(size_t)t * 4 + i] = make_float4(acc[i][0], acc[i][1], acc[i][2], acc[i][3]);
    __syncthreads();

    __shared__ float s_min[4][16];
    if (t < 64) {                              // thread = (i = t>>4, jq2 = t&15)
        const int i   = t >> 4;
        const int jq2 = t & 15;
        float4 s = make_float4(0.f, 0.f, 0.f, 0.f);
        #pragma unroll
        for (int k2 = 0; k2 < 16; ++k2) {
            float4 v = red4[(size_t)(k2 * 16 + jq2) * 4 + i];
            s.x += v.x; s.y += v.y; s.z += v.z; s.w += v.w;
        }
        const int ig = ib + i;
        const int jb = jt * 64 + 4 * jq2;
        float m = CUDART_INF_F;
        if (jb + 0 != ig) m = fminf(m, s.x);
        if (jb + 1 != ig) m = fminf(m, s.y);
        if (jb + 2 != ig) m = fminf(m, s.z);
        if (jb + 3 != ig) m = fminf(m, s.w);
        s_min[i][jq2] = m;
    }
    __syncthreads();
    if (t < 4) {
        float m = CUDART_INF_F;
        #pragma unroll
        for (int q = 0; q < 16; ++q) m = fminf(m, s_min[t][q]);
        g_partmin[(size_t)jt * NC + ib + t] = m;
    }

    // fan-in: last block computes sum(1 - min over jt) into out[0]
    __threadfence();
    __shared__ unsigned int s_prev;
    if (t == 0) s_prev = atomicAdd(&g_cnt2, 1u);
    __syncthreads();
    if (s_prev != NBLK2 - 1) return;
    __threadfence();

    float m = __ldcg(&g_partmin[t]);
    #pragma unroll
    for (int jt2 = 1; jt2 < NJT; ++jt2)
        m = fminf(m, __ldcg(&g_partmin[(size_t)jt2 * NC + t]));
    float v = 1.0f - m;

    #pragma unroll
    for (int o = 16; o > 0; o >>= 1)
        v += __shfl_xor_sync(0xffffffffu, v, o);

    __shared__ float sfin[8];
    if ((t & 31) == 0) sfin[t >> 5] = v;
    __syncthreads();
    if (t == 0) {
        float total = 0.f;
        #pragma unroll
        for (int i = 0; i < 8; ++i) total += sfin[i];
        out[0] = total;
        g_cnt2 = 0u;   // reset for next graph replay
    }
}

extern "C" void kernel_launch(void* const* d_in, const int* in_sizes, int n_in,
                              void* d_out, int out_size) {
    const float* feat = (const float*)d_in[0];
    float* out = (float*)d_out;

    centers_partial_kernel<<<NC * RSPLIT, 128>>>(feat);

    // PDL: launch dependents with programmatic stream serialization so their
    // blocks are scheduled while the predecessor drains; they gate on
    // cudaGridDependencySynchronize() before touching predecessor output.
    cudaLaunchAttribute attr[1];
    attr[0].id = cudaLaunchAttributeProgrammaticStreamSerialization;
    attr[0].val.programmaticStreamSerializationAllowed = 1;

    {
        cudaLaunchConfig_t cfg = {};
        cfg.gridDim  = dim3(NC, 1, 1);
        cfg.blockDim = dim3(128, 1, 1);
        cfg.attrs    = attr;
        cfg.numAttrs = 1;
        cudaLaunchKernelEx(&cfg, centers_finalize_kernel);
    }
    {
        cudaLaunchConfig_t cfg = {};
        cfg.gridDim  = dim3(NBLK2, 1, 1);
        cfg.blockDim = dim3(256, 1, 1);
        cfg.attrs    = attr;
        cfg.numAttrs = 1;
        cudaLaunchKernelEx(&cfg, sim_kernel, out);
    }
}

// round 12
// speedup vs baseline: 1.1160x; 1.0009x over previous
#include <cuda_runtime.h>
#include <math_constants.h>

#define NFEAT 65536
#define FD    512
#define NC    256
#define RPC   (NFEAT / NC)      // 256 rows per class
#define F4D   (FD / 4)          // 128 float4 per row
#define RSPLIT 8                // row-chunks per class
#define RCHUNK (RPC / RSPLIT)   // 32 rows per chunk
#define NIT    32               // i-tiles (8 rows each)
#define NJT    8                // j-tiles (32 cols each)
#define NBLK2  (NIT * NJT)      // 256 sim blocks

// Scratch (no cudaMalloc allowed)
__device__ float g_partial[RSPLIT * NC * FD];  // 4 MB partial sums
__device__ float g_centers[NC * FD];           // normalized centers [j][k]
__device__ float g_centersT[FD * NC];          // normalized centers [k][j]
__device__ float g_partmin[NJT * NC];          // per-(jtile,row) partial min
__device__ unsigned int g_cnt2;                // sim fan-in counter

// ---------------------------------------------------------------------------
// Kernel 1: partial row-sums. grid = 2048, block = 128.
// __launch_bounds__(128,8) -> 64-reg budget so ptxas keeps 8 LDG.128 live;
// 4 independent accumulator chains remove FADD serialization.
// ---------------------------------------------------------------------------
__global__ void __launch_bounds__(128, 8) centers_partial_kernel(const float* __restrict__ feat) {
    const int b = blockIdx.x;
    const int c = b >> 3;
    const int s = b & 7;
    const int t = threadIdx.x;

    const float4* __restrict__ p =
        reinterpret_cast<const float4*>(feat)
        + ((size_t)c * RPC + (size_t)s * RCHUNK) * F4D + t;

    float4 a0 = make_float4(0.f, 0.f, 0.f, 0.f);
    float4 a1 = make_float4(0.f, 0.f, 0.f, 0.f);
    float4 a2 = make_float4(0.f, 0.f, 0.f, 0.f);
    float4 a3 = make_float4(0.f, 0.f, 0.f, 0.f);
    #pragma unroll
    for (int r0 = 0; r0 < RCHUNK; r0 += 8) {
        float4 b0 = __ldcs(p + (size_t)(r0 + 0) * F4D);
        float4 b1 = __ldcs(p + (size_t)(r0 + 1) * F4D);
        float4 b2 = __ldcs(p + (size_t)(r0 + 2) * F4D);
        float4 b3 = __ldcs(p + (size_t)(r0 + 3) * F4D);
        float4 b4 = __ldcs(p + (size_t)(r0 + 4) * F4D);
        float4 b5 = __ldcs(p + (size_t)(r0 + 5) * F4D);
        float4 b6 = __ldcs(p + (size_t)(r0 + 6) * F4D);
        float4 b7 = __ldcs(p + (size_t)(r0 + 7) * F4D);
        a0.x += b0.x; a0.y += b0.y; a0.z += b0.z; a0.w += b0.w;
        a1.x += b1.x; a1.y += b1.y; a1.z += b1.z; a1.w += b1.w;
        a2.x += b2.x; a2.y += b2.y; a2.z += b2.z; a2.w += b2.w;
        a3.x += b3.x; a3.y += b3.y; a3.z += b3.z; a3.w += b3.w;
        a0.x += b4.x; a0.y += b4.y; a0.z += b4.z; a0.w += b4.w;
        a1.x += b5.x; a1.y += b5.y; a1.z += b5.z; a1.w += b5.w;
        a2.x += b6.x; a2.y += b6.y; a2.z += b6.z; a2.w += b6.w;
        a3.x += b7.x; a3.y += b7.y; a3.z += b7.z; a3.w += b7.w;
    }
    float4 acc = make_float4((a0.x + a1.x) + (a2.x + a3.x),
                             (a0.y + a1.y) + (a2.y + a3.y),
                             (a0.z + a1.z) + (a2.z + a3.z),
                             (a0.w + a1.w) + (a2.w + a3.w));
    reinterpret_cast<float4*>(g_partial)[((size_t)s * NC + c) * F4D + t] = acc;

#if __CUDA_ARCH__ >= 900
    cudaTriggerProgrammaticLaunchCompletion();
#endif
}

// ---------------------------------------------------------------------------
// Kernel 2: fold partials, mean, L2-norm; write row-major + transposed.
// grid = 256, block = 128. PDL secondary.
// ---------------------------------------------------------------------------
__global__ void __launch_bounds__(128) centers_finalize_kernel() {
#if __CUDA_ARCH__ >= 900
    cudaGridDependencySynchronize();
#endif
    const int c = blockIdx.x;
    const int t = threadIdx.x;

    float4 sum = make_float4(0.f, 0.f, 0.f, 0.f);
    #pragma unroll
    for (int k = 0; k < RSPLIT; ++k) {
        float4 v = reinterpret_cast<const float4*>(g_partial)[((size_t)k * NC + c) * F4D + t];
        sum.x += v.x; sum.y += v.y; sum.z += v.z; sum.w += v.w;
    }
    const float inv = 1.0f / (float)RPC;
    sum.x *= inv; sum.y *= inv; sum.z *= inv; sum.w *= inv;

    float ss = sum.x*sum.x + sum.y*sum.y + sum.z*sum.z + sum.w*sum.w;
    #pragma unroll
    for (int o = 16; o > 0; o >>= 1)
        ss += __shfl_xor_sync(0xffffffffu, ss, o);

    __shared__ float sred[4];
    if ((t & 31) == 0) sred[t >> 5] = ss;
    __syncthreads();
    float total = sred[0] + sred[1] + sred[2] + sred[3];
    float invn = 1.0f / fmaxf(sqrtf(total), 1e-8f);

    float4 o4 = make_float4(sum.x * invn, sum.y * invn, sum.z * invn, sum.w * invn);
    reinterpret_cast<float4*>(g_centers)[(size_t)c * F4D + t] = o4;

    g_centersT[(size_t)(4 * t + 0) * NC + c] = o4.x;
    g_centersT[(size_t)(4 * t + 1) * NC + c] = o4.y;
    g_centersT[(size_t)(4 * t + 2) * NC + c] = o4.z;
    g_centersT[(size_t)(4 * t + 3) * NC + c] = o4.w;

#if __CUDA_ARCH__ >= 900
    cudaTriggerProgrammaticLaunchCompletion();
#endif
}

// ---------------------------------------------------------------------------
// Kernel 3: sim row mins, 8 i-rows x 32 j per block = 256 blocks.
// Halves CT L2 traffic (16 MB total) at full grid width. Thread: jq = t&7
// owns float4 j-group (j = 32jt+4jq..+3); ks = t>>3 owns k in [16ks,16ks+16).
// 4 k-slices sharing a j-group are folded intra-warp via shfl (lanes jq,
// jq+8, jq+16, jq+24) -> red smem is only 8 warps x 8 jq x 8 i float4 = 8 KB.
// Last block: min over 8 j-tiles per row, sum(1 - min) -> out[0].
// ---------------------------------------------------------------------------
#define SIM_STEP8(A0, A1, A2, A3, A4, A5, A6, A7, V)                         \
    acc[0][0] += (A0)*(V).x; acc[0][1] += (A0)*(V).y;                        \
    acc[0][2] += (A0)*(V).z; acc[0][3] += (A0)*(V).w;                        \
    acc[1][0] += (A1)*(V).x; acc[1][1] += (A1)*(V).y;                        \
    acc[1][2] += (A1)*(V).z; acc[1][3] += (A1)*(V).w;                        \
    acc[2][0] += (A2)*(V).x; acc[2][1] += (A2)*(V).y;                        \
    acc[2][2] += (A2)*(V).z; acc[2][3] += (A2)*(V).w;                        \
    acc[3][0] += (A3)*(V).x; acc[3][1] += (A3)*(V).y;                        \
    acc[3][2] += (A3)*(V).z; acc[3][3] += (A3)*(V).w;                        \
    acc[4][0] += (A4)*(V).x; acc[4][1] += (A4)*(V).y;                        \
    acc[4][2] += (A4)*(V).z; acc[4][3] += (A4)*(V).w;                        \
    acc[5][0] += (A5)*(V).x; acc[5][1] += (A5)*(V).y;                        \
    acc[5][2] += (A5)*(V).z; acc[5][3] += (A5)*(V).w;                        \
    acc[6][0] += (A6)*(V).x; acc[6][1] += (A6)*(V).y;                        \
    acc[6][2] += (A6)*(V).z; acc[6][3] += (A6)*(V).w;                        \
    acc[7][0] += (A7)*(V).x; acc[7][1] += (A7)*(V).y;                        \
    acc[7][2] += (A7)*(V).z; acc[7][3] += (A7)*(V).w;

__global__ void __launch_bounds__(256) sim_kernel(float* __restrict__ out) {
    const int blk = blockIdx.x;
    const int bi  = blk & (NIT - 1);           // i-tile 0..31
    const int jt  = blk >> 5;                  // j-tile 0..7
    const int ib  = bi * 8;                    // i rows [ib, ib+8)
    const int t   = threadIdx.x;
    const int jq  = t & 7;                     // j float4-group within tile
    const int ks  = t >> 3;                    // k-slice 0..31 (16 k each)
    const int w   = t >> 5;                    // warp 0..7
    const int lane = t & 31;

#if __CUDA_ARCH__ >= 900
    cudaGridDependencySynchronize();
#endif

    __shared__ float4 sc4[8][F4D];             // 16 KB: i-rows
    __shared__ float4 redw[8][8][8];           // 8 KB: [warp][jq][i]
    {
        const float4* src = reinterpret_cast<const float4*>(g_centers + (size_t)ib * FD);
        for (int k = t; k < 8 * F4D; k += 256)
            sc4[k >> 7][k & 127] = src[k];
    }
    __syncthreads();

    const float4* __restrict__ ct = reinterpret_cast<const float4*>(g_centersT);
    const int col = jt * 8 + jq;               // float4 column in CT row

    float acc[8][4];
    #pragma unroll
    for (int i = 0; i < 8; ++i)
        #pragma unroll
        for (int j = 0; j < 4; ++j) acc[i][j] = 0.f;

    const int kb = ks * 16;
    float4 buf[2][4];
    #pragma unroll
    for (int u = 0; u < 4; ++u)
        buf[0][u] = __ldcg(&ct[(size_t)(kb + u) * (NC / 4) + col]);

    #pragma unroll
    for (int ch = 0; ch < 4; ++ch) {
        const int pb = ch & 1;
        if (ch < 3) {
            const int k2 = kb + (ch + 1) * 4;
            #pragma unroll
            for (int u = 0; u < 4; ++u)
                buf[pb ^ 1][u] = __ldcg(&ct[(size_t)(k2 + u) * (NC / 4) + col]);
        }
        const int kf = (kb + ch * 4) >> 2;
        float4 a0 = sc4[0][kf];
        float4 a1 = sc4[1][kf];
        float4 a2 = sc4[2][kf];
        float4 a3 = sc4[3][kf];
        float4 a4 = sc4[4][kf];
        float4 a5 = sc4[5][kf];
        float4 a6 = sc4[6][kf];
        float4 a7 = sc4[7][kf];
        SIM_STEP8(a0.x, a1.x, a2.x, a3.x, a4.x, a5.x, a6.x, a7.x, buf[pb][0]);
        SIM_STEP8(a0.y, a1.y, a2.y, a3.y, a4.y, a5.y, a6.y, a7.y, buf[pb][1]);
        SIM_STEP8(a0.z, a1.z, a2.z, a3.z, a4.z, a5.z, a6.z, a7.z, buf[pb][2]);
        SIM_STEP8(a0.w, a1.w, a2.w, a3.w, a4.w, a5.w, a6.w, a7.w, buf[pb][3]);
    }

    // intra-warp fold: lanes {jq, jq+8, jq+16, jq+24} share a j-group
    #pragma unroll
    for (int i = 0; i < 8; ++i)
        #pragma unroll
        for (int j = 0; j < 4; ++j) {
            acc[i][j] += __shfl_xor_sync(0xffffffffu, acc[i][j], 8);
            acc[i][j] += __shfl_xor_sync(0xffffffffu, acc[i][j], 16);
        }
    if (lane < 8) {
        #pragma unroll
        for (int i = 0; i < 8; ++i)
            redw[w][lane][i] = make_float4(acc[i][0], acc[i][1], acc[i][2], acc[i][3]);
    }
    __syncthreads();

    __shared__ float s_min[8][8];
    if (t < 64) {                              // thread = (i = t>>3, jq2 = t&7)
        const int i   = t >> 3;
        const int jq2 = t & 7;
        float4 s = make_float4(0.f, 0.f, 0.f, 0.f);
        #pragma unroll
        for (int w2 = 0; w2 < 8; ++w2) {
            float4 v = redw[w2][jq2][i];
            s.x += v.x; s.y += v.y; s.z += v.z; s.w += v.w;
        }
        const int ig = ib + i;
        const int jb = jt * 32 + 4 * jq2;
        float m = CUDART_INF_F;
        if (jb + 0 != ig) m = fminf(m, s.x);
        if (jb + 1 != ig) m = fminf(m, s.y);
        if (jb + 2 != ig) m = fminf(m, s.z);
        if (jb + 3 != ig) m = fminf(m, s.w);
        s_min[i][jq2] = m;
    }
    __syncthreads();
    if (t < 8) {
        float m = CUDART_INF_F;
        #pragma unroll
        for (int q = 0; q < 8; ++q) m = fminf(m, s_min[t][q]);
        g_partmin[(size_t)jt * NC + ib + t] = m;
    }

    // fan-in: last block computes sum(1 - min over jt) into out[0]
    __threadfence();
    __shared__ unsigned int s_prev;
    if (t == 0) s_prev = atomicAdd(&g_cnt2, 1u);
    __syncthreads();
    if (s_prev != NBLK2 - 1) return;
    __threadfence();

    float m = __ldcg(&g_partmin[t]);
    #pragma unroll
    for (int jt2 = 1; jt2 < NJT; ++jt2)
        m = fminf(m, __ldcg(&g_partmin[(size_t)jt2 * NC + t]));
    float v = 1.0f - m;

    #pragma unroll
    for (int o = 16; o > 0; o >>= 1)
        v += __shfl_xor_sync(0xffffffffu, v, o);

    __shared__ float sfin[8];
    if ((t & 31) == 0) sfin[t >> 5] = v;
    __syncthreads();
    if (t == 0) {
        float total = 0.f;
        #pragma unroll
        for (int i = 0; i < 8; ++i) total += sfin[i];
        out[0] = total;
        g_cnt2 = 0u;   // reset for next graph replay
    }
}

extern "C" void kernel_launch(void* const* d_in, const int* in_sizes, int n_in,
                              void* d_out, int out_size) {
    const float* feat = (const float*)d_in[0];
    float* out = (float*)d_out;

    centers_partial_kernel<<<NC * RSPLIT, 128>>>(feat);

    cudaLaunchAttribute attr[1];
    attr[0].id = cudaLaunchAttributeProgrammaticStreamSerialization;
    attr[0].val.programmaticStreamSerializationAllowed = 1;

    {
        cudaLaunchConfig_t cfg = {};
        cfg.gridDim  = dim3(NC, 1, 1);
        cfg.blockDim = dim3(128, 1, 1);
        cfg.attrs    = attr;
        cfg.numAttrs = 1;
        cudaLaunchKernelEx(&cfg, centers_finalize_kernel);
    }
    {
        cudaLaunchConfig_t cfg = {};
        cfg.gridDim  = dim3(NBLK2, 1, 1);
        cfg.blockDim = dim3(256, 1, 1);
        cfg.attrs    = attr;
        cfg.numAttrs = 1;
        cudaLaunchKernelEx(&cfg, sim_kernel, out);
    }
}